// round 15
// baseline (speedup 1.0000x reference)
#include <cuda_runtime.h>
#include <cstdint>

#define BATCH 8
#define SEQ   2048
#define DIM   1024

#define BM 128
#define BN 128
#define BK 16
#define TPB 256
#define LDR 132    // AV: padded [k][m] A stride (floats)
#define LDBD 264   // duplicated-B row stride (floats) = 128 pairs + 8 pad

typedef unsigned long long ull;

// 64MB transposed X scratch: g_xt[b][d][t]
__device__ float g_xt[(size_t)BATCH * DIM * SEQ];
__device__ float g_r0part[BATCH][64][DIM];

__device__ __forceinline__ void ffma2(ull& d, ull a, ull b) {
    asm("fma.rn.f32x2 %0, %1, %2, %0;" : "+l"(d) : "l"(a), "l"(b));
}
__device__ __forceinline__ ull dup2(float v) {
    ull r; asm("mov.b64 %0, {%1, %2};" : "=l"(r) : "f"(v), "f"(v)); return r;
}
__device__ __forceinline__ void unpk(ull p, float& lo, float& hi) {
    asm("mov.b64 {%0, %1}, %2;" : "=f"(lo), "=f"(hi) : "l"(p));
}
__device__ __forceinline__ uint32_t s2u(const void* p) {
    uint32_t a;
    asm("{ .reg .u64 t; cvta.to.shared.u64 t, %1; cvt.u32.u64 %0, t; }" : "=r"(a) : "l"(p));
    return a;
}
__device__ __forceinline__ void cpa16(uint32_t dst, const void* src) {
    asm volatile("cp.async.cg.shared.global [%0], [%1], 16;" :: "r"(dst), "l"(src));
}
#define CP_COMMIT() asm volatile("cp.async.commit_group;" ::: "memory")
#define CP_WAIT0()  asm volatile("cp.async.wait_group 0;" ::: "memory")

struct AccM { ull a[8][4]; };   // [n-col][m-pair]

// Inner loop with duplicated+permuted B: per k = 2 LDS.128 + 8 LDS.64 + 32 FFMA2.
// B layout: row k holds 128 dup'd pairs; pair for col n (n=4*tn+e lo / 64+4*tn+e hi)
// lives at slot 16*e+tn (lo) / 64+16*e+tn (hi); float offset = 2*slot.
template <int LDA_>
__device__ __forceinline__ void compute_dp(const float* __restrict__ As,
                                           const float* __restrict__ Bd,
                                           int tm, int tn, AccM& acc) {
#pragma unroll
    for (int k = 0; k < BK; k++) {
        const float* ar = As + k * LDA_;
        const float* br = Bd + k * LDBD + 2 * tn;
        ulonglong2 a01 = *(const ulonglong2*)&ar[tm * 4];
        ulonglong2 a23 = *(const ulonglong2*)&ar[64 + tm * 4];
        ull ap[4] = {a01.x, a01.y, a23.x, a23.y};
        ull bd[8];
#pragma unroll
        for (int e = 0; e < 4; e++) {
            bd[e]     = *(const ull*)&br[32 * e];
            bd[4 + e] = *(const ull*)&br[128 + 32 * e];
        }
#pragma unroll
        for (int v = 0; v < 8; v++)
#pragma unroll
            for (int p = 0; p < 4; p++) ffma2(acc.a[v][p], ap[p], bd[v]);
    }
}

__device__ __forceinline__ void store_tile(float* dst, size_t ld, int tm, int tn,
                                           const AccM& acc) {
#pragma unroll
    for (int u = 0; u < 8; u++) {
        const int p = u >> 1, hi = u & 1;
        const int r = (u < 4) ? (tm * 4 + u) : (64 + tm * 4 + (u - 4));
        float c[8];
#pragma unroll
        for (int v = 0; v < 8; v++) {
            float lo, hh;
            unpk(acc.a[v][p], lo, hh);
            c[v] = hi ? hh : lo;
        }
        *(float4*)&dst[(size_t)r * ld + tn * 4]      = make_float4(c[0], c[1], c[2], c[3]);
        *(float4*)&dst[(size_t)r * ld + 64 + tn * 4] = make_float4(c[4], c[5], c[6], c[7]);
    }
}

// Duplicated-B staging: thread (kS=t>>4, q=t&15) owns values n = 8q..8q+7 of row kS.
// slot(n=8q+j) = (q>=8?64:0) + 2*(q&7) + 16*(j&3) + (j>>2)  -> constant offsets in j.
__device__ __forceinline__ void stsBdup(float* __restrict__ Brow2, const float4& u0,
                                        const float4& u1) {
    // Brow2 = B stage + kS*LDBD + 2*base, base = (q&8)*8 + 2*(q&7)
    *(ull*)&Brow2[0]  = dup2(u0.x);
    *(ull*)&Brow2[32] = dup2(u0.y);
    *(ull*)&Brow2[64] = dup2(u0.z);
    *(ull*)&Brow2[96] = dup2(u0.w);
    *(ull*)&Brow2[2]  = dup2(u1.x);
    *(ull*)&Brow2[34] = dup2(u1.y);
    *(ull*)&Brow2[66] = dup2(u1.z);
    *(ull*)&Brow2[98] = dup2(u1.w);
}

// ---------------------------------------------------------------------------
// Transpose: g_xt[b][d][t] = x[b][t][d]
// ---------------------------------------------------------------------------
__global__ __launch_bounds__(256) void transpose_x(const float* __restrict__ x) {
    __shared__ float tile[32][33];
    const int b = blockIdx.z;
    const int t0 = blockIdx.x * 32, d0 = blockIdx.y * 32;
    const int tx = threadIdx.x & 31, ty = threadIdx.x >> 5;
    const float* X = x + (size_t)b * SEQ * DIM;
    float* Xt = g_xt + (size_t)b * DIM * SEQ;
#pragma unroll
    for (int j = 0; j < 32; j += 8)
        tile[ty + j][tx] = X[(size_t)(t0 + ty + j) * DIM + d0 + tx];
    __syncthreads();
#pragma unroll
    for (int j = 0; j < 32; j += 8)
        Xt[(size_t)(d0 + ty + j) * SEQ + t0 + tx] = tile[tx][ty + j];
}

// ---------------------------------------------------------------------------
// Kernel 1: scores S = X X^T, lower-tri tiles. A via cp.async from g_xt [k][m];
// B via LDG + dup-permute STS.64 from g_xt. 2-stage.
// ---------------------------------------------------------------------------
#define S_A_FLOATS 2048
#define S_STG (S_A_FLOATS + BK * LDBD)      // 2048 + 4224 = 6272 floats
#define S_SMEM (2 * S_STG * 4)              // 50176 B

__global__ __launch_bounds__(TPB, 2) void gemm_scores(float* __restrict__ Sg) {
    const int b = blockIdx.y;
    const int t = blockIdx.x;
    int it = (int)((sqrtf(8.f * (float)t + 1.f) - 1.f) * 0.5f);
    while ((it + 1) * (it + 2) / 2 <= t) ++it;
    while (it * (it + 1) / 2 > t) --it;
    const int jt = t - it * (it + 1) / 2;

    extern __shared__ float sm[];
    const float* Xt = g_xt + (size_t)b * DIM * SEQ;
    float* Sb = Sg + (size_t)b * SEQ * SEQ;

    const int tid = threadIdx.x;
    const int tm = tid / 16, tn = tid % 16;
    const int i0 = it * BM, j0 = jt * BN;
    const int lk = tid >> 5, lm4 = (tid & 31) << 2;            // A cp.async mapping
    const int kS = tid >> 4, q = tid & 15, n0 = q * 8;          // B staging mapping
    const int bBase = (q & 8) * 16 + 4 * (q & 7);               // 2*base floats

    AccM acc;
#pragma unroll
    for (int v = 0; v < 8; v++)
#pragma unroll
        for (int p = 0; p < 4; p++) acc.a[v][p] = 0ull;

    float4 u0, u1;
    auto cpaA = [&](int s, int c) {
        const int kk = c * BK;
        float* As = sm + s * S_STG;
#pragma unroll
        for (int itr = 0; itr < 2; itr++) {
            const int k = lk + itr * 8;
            cpa16(s2u(&As[k * 128 + lm4]), &Xt[(size_t)(kk + k) * SEQ + i0 + lm4]);
        }
        CP_COMMIT();
    };
    auto ldgB = [&](int c) {
        const float* src = &Xt[(size_t)(c * BK + kS) * SEQ + j0 + n0];
        u0 = *(const float4*)&src[0];
        u1 = *(const float4*)&src[4];
    };
    auto stsB = [&](int s) {
        stsBdup(sm + s * S_STG + S_A_FLOATS + kS * LDBD + bBase, u0, u1);
    };

    const int NC = DIM / BK;   // 64
    ldgB(0);
    cpaA(0, 0);
    stsB(0);
    CP_WAIT0();
    __syncthreads();
    for (int c = 0; c < NC; c++) {
        if (c + 1 < NC) { ldgB(c + 1); cpaA((c + 1) & 1, c + 1); }
        const float* stg = sm + (c & 1) * S_STG;
        compute_dp<128>(stg, stg + S_A_FLOATS, tm, tn, acc);
        if (c + 1 < NC) { stsB((c + 1) & 1); CP_WAIT0(); }
        __syncthreads();
    }
    store_tile(&Sb[(size_t)i0 * SEQ + j0], SEQ, tm, tn, acc);
}

// ---------------------------------------------------------------------------
// Kernel 2: softmax rows (strict-lower causal; row0 uniform 1/T), float4.
// ---------------------------------------------------------------------------
__global__ __launch_bounds__(256) void softmax_rows(float* __restrict__ Wg) {
    const int i = blockIdx.x, b = blockIdx.y;
    float* row = Wg + ((size_t)b * SEQ + i) * SEQ;
    const int tid = threadIdx.x;
    if (i == 0) {
        const float v = 1.0f / (float)SEQ;
        const float4 v4 = make_float4(v, v, v, v);
#pragma unroll
        for (int s = 0; s < 2; s++) *(float4*)&row[(tid + s * 256) * 4] = v4;
        return;
    }
    float vals[8];
    float m = -3.0e38f;
#pragma unroll
    for (int s = 0; s < 2; s++) {
        const int j4 = (tid + s * 256) * 4;
        if (j4 < i) {
            float4 v = *(const float4*)&row[j4];
            vals[s * 4 + 0] = (j4 + 0 < i) ? v.x : -3.0e38f;
            vals[s * 4 + 1] = (j4 + 1 < i) ? v.y : -3.0e38f;
            vals[s * 4 + 2] = (j4 + 2 < i) ? v.z : -3.0e38f;
            vals[s * 4 + 3] = (j4 + 3 < i) ? v.w : -3.0e38f;
        } else {
            vals[s * 4 + 0] = vals[s * 4 + 1] = vals[s * 4 + 2] = vals[s * 4 + 3] = -3.0e38f;
        }
#pragma unroll
        for (int e = 0; e < 4; e++) m = fmaxf(m, vals[s * 4 + e]);
    }
    __shared__ float sred[8];
#pragma unroll
    for (int o = 16; o; o >>= 1) m = fmaxf(m, __shfl_xor_sync(0xffffffffu, m, o));
    if ((tid & 31) == 0) sred[tid >> 5] = m;
    __syncthreads();
    m = sred[0];
#pragma unroll
    for (int w = 1; w < 8; w++) m = fmaxf(m, sred[w]);
    float l = 0.f;
#pragma unroll
    for (int s = 0; s < 8; s++) {
        float e = (vals[s] > -1.0e38f) ? __expf(vals[s] - m) : 0.f;
        vals[s] = e;
        l += e;
    }
#pragma unroll
    for (int o = 16; o; o >>= 1) l += __shfl_xor_sync(0xffffffffu, l, o);
    __syncthreads();
    if ((tid & 31) == 0) sred[tid >> 5] = l;
    __syncthreads();
    l = 0.f;
#pragma unroll
    for (int w = 0; w < 8; w++) l += sred[w];
    const float inv = 1.0f / l;
#pragma unroll
    for (int s = 0; s < 2; s++) {
        const int j4 = (tid + s * 256) * 4;
        *(float4*)&row[j4] = make_float4(vals[s * 4 + 0] * inv, vals[s * 4 + 1] * inv,
                                         vals[s * 4 + 2] * inv, vals[s * 4 + 3] * inv);
    }
}

// ---------------------------------------------------------------------------
// Kernel 3: O = W @ X. A (W) LDG + transposed STS [k][m] (LDR); B (X) LDG +
// dup-permute STS.64. K bounded at (it+1)*BM; heavy-first.
// ---------------------------------------------------------------------------
#define V_A_FLOATS (BK * LDR)               // 2112
#define V_STG (V_A_FLOATS + BK * LDBD)      // 2112 + 4224 = 6336 floats
#define V_SMEM (2 * V_STG * 4)              // 50688 B

__global__ __launch_bounds__(TPB, 2) void gemm_av(const float* __restrict__ Wg,
                                                  const float* __restrict__ x,
                                                  float* __restrict__ Og) {
    const int b = blockIdx.z, dt = blockIdx.x;
    const int it = (SEQ / BM - 1) - blockIdx.y;   // heavy-first

    extern __shared__ float sm[];
    const float* W = Wg + (size_t)b * SEQ * SEQ;
    const float* X = x + (size_t)b * SEQ * DIM;
    float* Ob = Og + (size_t)b * SEQ * DIM;

    const int tid = threadIdx.x;
    const int tm = tid / 16, tn = tid % 16;
    const int i0 = it * BM, d0 = dt * BN;
    const int lrA = tid / 4, lcA = (tid % 4) * 4;               // A staging mapping
    const int kS = tid >> 4, q = tid & 15, n0 = q * 8;           // B staging mapping
    const int bBase = (q & 8) * 16 + 4 * (q & 7);

    AccM acc;
#pragma unroll
    for (int v = 0; v < 8; v++)
#pragma unroll
        for (int p = 0; p < 4; p++) acc.a[v][p] = 0ull;

    float4 a0, a1, u0, u1;
    auto ldgA = [&](int k0) {
        a0 = *(const float4*)&W[(size_t)(i0 + lrA)      * SEQ + k0 + lcA];
        a1 = *(const float4*)&W[(size_t)(i0 + lrA + 64) * SEQ + k0 + lcA];
    };
    auto stsA = [&](int s) {
        float* As = sm + s * V_STG;
        As[(lcA + 0) * LDR + lrA] = a0.x; As[(lcA + 1) * LDR + lrA] = a0.y;
        As[(lcA + 2) * LDR + lrA] = a0.z; As[(lcA + 3) * LDR + lrA] = a0.w;
        As[(lcA + 0) * LDR + lrA + 64] = a1.x; As[(lcA + 1) * LDR + lrA + 64] = a1.y;
        As[(lcA + 2) * LDR + lrA + 64] = a1.z; As[(lcA + 3) * LDR + lrA + 64] = a1.w;
    };
    auto ldgB = [&](int c) {
        const float* src = &X[(size_t)(c * BK + kS) * DIM + d0 + n0];
        u0 = *(const float4*)&src[0];
        u1 = *(const float4*)&src[4];
    };
    auto stsB = [&](int s) {
        stsBdup(sm + s * V_STG + V_A_FLOATS + kS * LDBD + bBase, u0, u1);
    };

    const int NC = (it + 1) * (BM / BK);   // causal K bound
    ldgA(0);
    ldgB(0);
    stsA(0);
    stsB(0);
    __syncthreads();
    for (int c = 0; c < NC; c++) {
        if (c + 1 < NC) { ldgA((c + 1) * BK); ldgB(c + 1); }
        const float* stg = sm + (c & 1) * V_STG;
        compute_dp<LDR>(stg, stg + V_A_FLOATS, tm, tn, acc);
        if (c + 1 < NC) { stsA((c + 1) & 1); stsB((c + 1) & 1); }
        __syncthreads();
    }
    store_tile(&Ob[(size_t)i0 * DIM + d0], DIM, tm, tn, acc);
}

// ---------------------------------------------------------------------------
// Row 0: att_vec[b,0,:] = mean_j x[b,j,:]  (two-stage, 64 slices/batch)
// ---------------------------------------------------------------------------
__global__ __launch_bounds__(256) void r0_partial(const float* __restrict__ x) {
    const int b = blockIdx.y, sl = blockIdx.x;
    const float* X = x + (size_t)b * SEQ * DIM;
    const int tid = threadIdx.x;
    float s[4] = {0.f, 0.f, 0.f, 0.f};
    const int j0 = sl * 32;
    for (int j = j0; j < j0 + 32; j++) {
#pragma unroll
        for (int q = 0; q < 4; q++) s[q] += X[(size_t)j * DIM + tid + q * 256];
    }
#pragma unroll
    for (int q = 0; q < 4; q++) g_r0part[b][sl][tid + q * 256] = s[q];
}

__global__ __launch_bounds__(256) void r0_reduce(float* __restrict__ Og) {
    const int b = blockIdx.y;
    const int d = blockIdx.x * 256 + threadIdx.x;
    float s = 0.f;
#pragma unroll
    for (int sl = 0; sl < 64; sl++) s += g_r0part[b][sl][d];
    Og[(size_t)b * SEQ * DIM + d] = s * (1.0f / (float)SEQ);
}

// ---------------------------------------------------------------------------
extern "C" void kernel_launch(void* const* d_in, const int* in_sizes, int n_in,
                              void* d_out, int out_size) {
    const float* x = (const float*)d_in[0];
    float* out     = (float*)d_out;
    float* att_vec = out;                                   // [B,T,D]
    float* Wg      = out + (size_t)BATCH * SEQ * DIM;       // [B,T,T]

    cudaFuncSetAttribute(gemm_scores, cudaFuncAttributeMaxDynamicSharedMemorySize, S_SMEM);
    cudaFuncSetAttribute(gemm_av, cudaFuncAttributeMaxDynamicSharedMemorySize, V_SMEM);

    dim3 gt(SEQ / 32, DIM / 32, BATCH);
    transpose_x<<<gt, 256>>>(x);

    const int NT = SEQ / BM;                  // 16
    dim3 g1(NT * (NT + 1) / 2, BATCH);        // 136 lower-tri tiles/batch
    gemm_scores<<<g1, TPB, S_SMEM>>>(Wg);

    dim3 g2(SEQ, BATCH);
    softmax_rows<<<g2, 256>>>(Wg);

    dim3 g3(DIM / BN, SEQ / BM, BATCH);
    gemm_av<<<g3, TPB, V_SMEM>>>(Wg, x, att_vec);

    dim3 g4(64, BATCH);
    r0_partial<<<g4, 256>>>(x);
    dim3 g5(DIM / 256, BATCH);
    r0_reduce<<<g5, 256>>>(att_vec);
}

// round 16
// speedup vs baseline: 1.2181x; 1.2181x over previous
#include <cuda_runtime.h>
#include <cstdint>

#define BATCH 8
#define SEQ   2048
#define DIM   1024

#define BM 128
#define BN 128
#define BK 16
#define TPB 256

typedef unsigned long long ull;

// Scratch: transposed X (64MB) and transposed W (128MB). g_wt upper-tri tiles
// are never written and stay zero from static zero-init (matches softmax zeros).
__device__ float g_xt[(size_t)BATCH * DIM * SEQ];
__device__ float g_wt[(size_t)BATCH * SEQ * SEQ];
__device__ float g_r0part[BATCH][64][DIM];

__device__ __forceinline__ void ffma2(ull& d, ull a, ull b) {
    asm("fma.rn.f32x2 %0, %1, %2, %0;" : "+l"(d) : "l"(a), "l"(b));
}
__device__ __forceinline__ ull dup2(float v) {
    ull r; asm("mov.b64 %0, {%1, %2};" : "=l"(r) : "f"(v), "f"(v)); return r;
}
__device__ __forceinline__ void unpk(ull p, float& lo, float& hi) {
    asm("mov.b64 {%0, %1}, %2;" : "=f"(lo), "=f"(hi) : "l"(p));
}
__device__ __forceinline__ uint32_t s2u(const void* p) {
    uint32_t a;
    asm("{ .reg .u64 t; cvta.to.shared.u64 t, %1; cvt.u32.u64 %0, t; }" : "=r"(a) : "l"(p));
    return a;
}
__device__ __forceinline__ void cpa16(uint32_t dst, const void* src) {
    asm volatile("cp.async.cg.shared.global [%0], [%1], 16;" :: "r"(dst), "l"(src));
}
#define CP_COMMIT() asm volatile("cp.async.commit_group;" ::: "memory")
#define CP_WAIT1()  asm volatile("cp.async.wait_group 1;" ::: "memory")
#define CP_WAIT0()  asm volatile("cp.async.wait_group 0;" ::: "memory")

struct AccM { ull a[8][4]; };   // [n-col][m-pair]

// m-packed inner product: As [k][m], Bs [k][n], both stride 128.
// Per k: 4x LDS.128 + 8 mov.b64 + 32 FFMA2. (Validated optimum.)
__device__ __forceinline__ void compute_mp(const float* __restrict__ As,
                                           const float* __restrict__ Bs,
                                           int tm, int tn, AccM& acc) {
#pragma unroll
    for (int k = 0; k < BK; k++) {
        ulonglong2 a01 = *(const ulonglong2*)&As[k * 128 + tm * 4];
        ulonglong2 a23 = *(const ulonglong2*)&As[k * 128 + 64 + tm * 4];
        float4 b0 = *(const float4*)&Bs[k * 128 + tn * 4];
        float4 b1 = *(const float4*)&Bs[k * 128 + 64 + tn * 4];
        ull ap[4] = {a01.x, a01.y, a23.x, a23.y};
        ull bd[8] = {dup2(b0.x), dup2(b0.y), dup2(b0.z), dup2(b0.w),
                     dup2(b1.x), dup2(b1.y), dup2(b1.z), dup2(b1.w)};
#pragma unroll
        for (int v = 0; v < 8; v++)
#pragma unroll
            for (int p = 0; p < 4; p++) ffma2(acc.a[v][p], ap[p], bd[v]);
    }
}

__device__ __forceinline__ void store_tile(float* dst, size_t ld, int tm, int tn,
                                           const AccM& acc) {
#pragma unroll
    for (int u = 0; u < 8; u++) {
        const int p = u >> 1, hi = u & 1;
        const int r = (u < 4) ? (tm * 4 + u) : (64 + tm * 4 + (u - 4));
        float c[8];
#pragma unroll
        for (int v = 0; v < 8; v++) {
            float lo, hh;
            unpk(acc.a[v][p], lo, hh);
            c[v] = hi ? hh : lo;
        }
        *(float4*)&dst[(size_t)r * ld + tn * 4]      = make_float4(c[0], c[1], c[2], c[3]);
        *(float4*)&dst[(size_t)r * ld + 64 + tn * 4] = make_float4(c[4], c[5], c[6], c[7]);
    }
}

// ---------------------------------------------------------------------------
// Transpose X: g_xt[b][d][t] = x[b][t][d]
// ---------------------------------------------------------------------------
__global__ __launch_bounds__(256) void transpose_x(const float* __restrict__ x) {
    __shared__ float tile[32][33];
    const int b = blockIdx.z;
    const int t0 = blockIdx.x * 32, d0 = blockIdx.y * 32;
    const int tx = threadIdx.x & 31, ty = threadIdx.x >> 5;
    const float* X = x + (size_t)b * SEQ * DIM;
    float* Xt = g_xt + (size_t)b * DIM * SEQ;
#pragma unroll
    for (int j = 0; j < 32; j += 8)
        tile[ty + j][tx] = X[(size_t)(t0 + ty + j) * DIM + d0 + tx];
    __syncthreads();
#pragma unroll
    for (int j = 0; j < 32; j += 8)
        Xt[(size_t)(d0 + ty + j) * SEQ + t0 + tx] = tile[tx][ty + j];
}

// ---------------------------------------------------------------------------
// Transpose W (lower-tri 32-tiles only): g_wt[b][j][i] = W[b][i][j].
// Tiles with tj > ti are all-zero in W (softmax) and never written to g_wt
// (stay zero from static init).
// ---------------------------------------------------------------------------
__global__ __launch_bounds__(256) void transpose_w(const float* __restrict__ Wg) {
    const int ti = blockIdx.y, tj = blockIdx.x;
    if (tj > ti) return;
    __shared__ float tile[32][33];
    const int b = blockIdx.z;
    const int r0 = ti * 32, c0 = tj * 32;
    const int tx = threadIdx.x & 31, ty = threadIdx.x >> 5;
    const float* W = Wg + (size_t)b * SEQ * SEQ;
    float* Wt = g_wt + (size_t)b * SEQ * SEQ;
#pragma unroll
    for (int j = 0; j < 32; j += 8)
        tile[ty + j][tx] = W[(size_t)(r0 + ty + j) * SEQ + c0 + tx];
    __syncthreads();
#pragma unroll
    for (int j = 0; j < 32; j += 8)
        Wt[(size_t)(c0 + ty + j) * SEQ + r0 + tx] = tile[tx][ty + j];
}

// ---------------------------------------------------------------------------
// Kernel 1: scores S = X X^T, lower-tri tiles; operands from g_xt [k][m].
// 3-stage cp.async pipeline (R13, measured ~610us).
// ---------------------------------------------------------------------------
#define S_STAGE 4096                        // floats per stage (A 2048 | B 2048)
#define S_SMEM  (3 * S_STAGE * 4)           // 49152 B

__global__ __launch_bounds__(TPB, 2) void gemm_scores(float* __restrict__ Sg) {
    const int b = blockIdx.y;
    const int t = blockIdx.x;
    int it = (int)((sqrtf(8.f * (float)t + 1.f) - 1.f) * 0.5f);
    while ((it + 1) * (it + 2) / 2 <= t) ++it;
    while (it * (it + 1) / 2 > t) --it;
    const int jt = t - it * (it + 1) / 2;

    extern __shared__ float sm[];
    const float* Xt = g_xt + (size_t)b * DIM * SEQ;
    float* Sb = Sg + (size_t)b * SEQ * SEQ;

    const int tid = threadIdx.x;
    const int tm = tid / 16, tn = tid % 16;
    const int i0 = it * BM, j0 = jt * BN;
    const int lk = tid >> 5, lm4 = (tid & 31) << 2;

    AccM acc;
#pragma unroll
    for (int v = 0; v < 8; v++)
#pragma unroll
        for (int p = 0; p < 4; p++) acc.a[v][p] = 0ull;

    auto ldg = [&](int s, int c) {
        const int kk = c * BK;
        float* As = sm + s * S_STAGE;
        float* Bs = As + 2048;
#pragma unroll
        for (int itr = 0; itr < 2; itr++) {
            const int k = lk + itr * 8;
            cpa16(s2u(&As[k * 128 + lm4]), &Xt[(size_t)(kk + k) * SEQ + i0 + lm4]);
            cpa16(s2u(&Bs[k * 128 + lm4]), &Xt[(size_t)(kk + k) * SEQ + j0 + lm4]);
        }
        CP_COMMIT();
    };

    const int NC = DIM / BK;   // 64
    ldg(0, 0);
    ldg(1, 1);
    for (int c = 0; c < NC; c++) {
        if (c + 1 < NC) { CP_WAIT1(); } else { CP_WAIT0(); }
        __syncthreads();
        if (c + 2 < NC) ldg((c + 2) % 3, c + 2);
        compute_mp(sm + (c % 3) * S_STAGE, sm + (c % 3) * S_STAGE + 2048, tm, tn, acc);
    }
    store_tile(&Sb[(size_t)i0 * SEQ + j0], SEQ, tm, tn, acc);
}

// ---------------------------------------------------------------------------
// Kernel 2: softmax rows (strict-lower causal; row0 uniform 1/T), float4.
// ---------------------------------------------------------------------------
__global__ __launch_bounds__(256) void softmax_rows(float* __restrict__ Wg) {
    const int i = blockIdx.x, b = blockIdx.y;
    float* row = Wg + ((size_t)b * SEQ + i) * SEQ;
    const int tid = threadIdx.x;
    if (i == 0) {
        const float v = 1.0f / (float)SEQ;
        const float4 v4 = make_float4(v, v, v, v);
#pragma unroll
        for (int s = 0; s < 2; s++) *(float4*)&row[(tid + s * 256) * 4] = v4;
        return;
    }
    float vals[8];
    float m = -3.0e38f;
#pragma unroll
    for (int s = 0; s < 2; s++) {
        const int j4 = (tid + s * 256) * 4;
        if (j4 < i) {
            float4 v = *(const float4*)&row[j4];
            vals[s * 4 + 0] = (j4 + 0 < i) ? v.x : -3.0e38f;
            vals[s * 4 + 1] = (j4 + 1 < i) ? v.y : -3.0e38f;
            vals[s * 4 + 2] = (j4 + 2 < i) ? v.z : -3.0e38f;
            vals[s * 4 + 3] = (j4 + 3 < i) ? v.w : -3.0e38f;
        } else {
            vals[s * 4 + 0] = vals[s * 4 + 1] = vals[s * 4 + 2] = vals[s * 4 + 3] = -3.0e38f;
        }
#pragma unroll
        for (int e = 0; e < 4; e++) m = fmaxf(m, vals[s * 4 + e]);
    }
    __shared__ float sred[8];
#pragma unroll
    for (int o = 16; o; o >>= 1) m = fmaxf(m, __shfl_xor_sync(0xffffffffu, m, o));
    if ((tid & 31) == 0) sred[tid >> 5] = m;
    __syncthreads();
    m = sred[0];
#pragma unroll
    for (int w = 1; w < 8; w++) m = fmaxf(m, sred[w]);
    float l = 0.f;
#pragma unroll
    for (int s = 0; s < 8; s++) {
        float e = (vals[s] > -1.0e38f) ? __expf(vals[s] - m) : 0.f;
        vals[s] = e;
        l += e;
    }
#pragma unroll
    for (int o = 16; o; o >>= 1) l += __shfl_xor_sync(0xffffffffu, l, o);
    __syncthreads();
    if ((tid & 31) == 0) sred[tid >> 5] = l;
    __syncthreads();
    l = 0.f;
#pragma unroll
    for (int w = 0; w < 8; w++) l += sred[w];
    const float inv = 1.0f / l;
#pragma unroll
    for (int s = 0; s < 2; s++) {
        const int j4 = (tid + s * 256) * 4;
        *(float4*)&row[j4] = make_float4(vals[s * 4 + 0] * inv, vals[s * 4 + 1] * inv,
                                         vals[s * 4 + 2] * inv, vals[s * 4 + 3] * inv);
    }
}

// ---------------------------------------------------------------------------
// Kernel 3: O = W @ X — structurally identical to gemm_scores.
// A from g_wt [k][m] (pre-transposed W), B from x [k][d]; both cp.async,
// 3-stage. K bounded at (it+1)*BM; heavy tiles first.
// ---------------------------------------------------------------------------
__global__ __launch_bounds__(TPB, 2) void gemm_av(const float* __restrict__ x,
                                                  float* __restrict__ Og) {
    const int b = blockIdx.z, dt = blockIdx.x;
    const int it = (SEQ / BM - 1) - blockIdx.y;   // heavy-first

    extern __shared__ float sm[];
    const float* Wt = g_wt + (size_t)b * SEQ * SEQ;
    const float* X = x + (size_t)b * SEQ * DIM;
    float* Ob = Og + (size_t)b * SEQ * DIM;

    const int tid = threadIdx.x;
    const int tm = tid / 16, tn = tid % 16;
    const int i0 = it * BM, d0 = dt * BN;
    const int lk = tid >> 5, lm4 = (tid & 31) << 2;

    AccM acc;
#pragma unroll
    for (int v = 0; v < 8; v++)
#pragma unroll
        for (int p = 0; p < 4; p++) acc.a[v][p] = 0ull;

    auto ldg = [&](int s, int c) {
        const int kk = c * BK;
        float* As = sm + s * S_STAGE;
        float* Bs = As + 2048;
#pragma unroll
        for (int itr = 0; itr < 2; itr++) {
            const int k = lk + itr * 8;
            cpa16(s2u(&As[k * 128 + lm4]), &Wt[(size_t)(kk + k) * SEQ + i0 + lm4]);
            cpa16(s2u(&Bs[k * 128 + lm4]), &X[(size_t)(kk + k) * DIM + d0 + lm4]);
        }
        CP_COMMIT();
    };

    const int NC = (it + 1) * (BM / BK);   // causal K bound (>= 8)
    ldg(0, 0);
    ldg(1, 1);
    for (int c = 0; c < NC; c++) {
        if (c + 1 < NC) { CP_WAIT1(); } else { CP_WAIT0(); }
        __syncthreads();
        if (c + 2 < NC) ldg((c + 2) % 3, c + 2);
        compute_mp(sm + (c % 3) * S_STAGE, sm + (c % 3) * S_STAGE + 2048, tm, tn, acc);
    }
    store_tile(&Ob[(size_t)i0 * DIM + d0], DIM, tm, tn, acc);
}

// ---------------------------------------------------------------------------
// Row 0: att_vec[b,0,:] = mean_j x[b,j,:]  (two-stage, 64 slices/batch)
// ---------------------------------------------------------------------------
__global__ __launch_bounds__(256) void r0_partial(const float* __restrict__ x) {
    const int b = blockIdx.y, sl = blockIdx.x;
    const float* X = x + (size_t)b * SEQ * DIM;
    const int tid = threadIdx.x;
    float s[4] = {0.f, 0.f, 0.f, 0.f};
    const int j0 = sl * 32;
    for (int j = j0; j < j0 + 32; j++) {
#pragma unroll
        for (int q = 0; q < 4; q++) s[q] += X[(size_t)j * DIM + tid + q * 256];
    }
#pragma unroll
    for (int q = 0; q < 4; q++) g_r0part[b][sl][tid + q * 256] = s[q];
}

__global__ __launch_bounds__(256) void r0_reduce(float* __restrict__ Og) {
    const int b = blockIdx.y;
    const int d = blockIdx.x * 256 + threadIdx.x;
    float s = 0.f;
#pragma unroll
    for (int sl = 0; sl < 64; sl++) s += g_r0part[b][sl][d];
    Og[(size_t)b * SEQ * DIM + d] = s * (1.0f / (float)SEQ);
}

// ---------------------------------------------------------------------------
extern "C" void kernel_launch(void* const* d_in, const int* in_sizes, int n_in,
                              void* d_out, int out_size) {
    const float* x = (const float*)d_in[0];
    float* out     = (float*)d_out;
    float* att_vec = out;                                   // [B,T,D]
    float* Wg      = out + (size_t)BATCH * SEQ * DIM;       // [B,T,T]

    cudaFuncSetAttribute(gemm_scores, cudaFuncAttributeMaxDynamicSharedMemorySize, S_SMEM);
    cudaFuncSetAttribute(gemm_av, cudaFuncAttributeMaxDynamicSharedMemorySize, S_SMEM);

    dim3 gt(SEQ / 32, DIM / 32, BATCH);
    transpose_x<<<gt, 256>>>(x);

    const int NT = SEQ / BM;                  // 16
    dim3 g1(NT * (NT + 1) / 2, BATCH);        // 136 lower-tri tiles/batch
    gemm_scores<<<g1, TPB, S_SMEM>>>(Wg);

    dim3 g2(SEQ, BATCH);
    softmax_rows<<<g2, 256>>>(Wg);

    dim3 gw(SEQ / 32, SEQ / 32, BATCH);       // lower-tri tiles do work
    transpose_w<<<gw, 256>>>(Wg);

    dim3 g3(DIM / BN, SEQ / BM, BATCH);
    gemm_av<<<g3, TPB, S_SMEM>>>(x, att_vec);

    dim3 g4(64, BATCH);
    r0_partial<<<g4, 256>>>(x);
    dim3 g5(DIM / 256, BATCH);
    r0_reduce<<<g5, 256>>>(att_vec);
}